// round 2
// baseline (speedup 1.0000x reference)
#include <cuda_runtime.h>

// ---------------------------------------------------------------------------
// BCNet: logits[b,h,v,q] = sum_k h_mat[h,k] * relu(v@Wv^T+bv)[b,v,k]
//                                          * relu(q@Wq^T+bq)[b,q,k] + h_bias[h]
// Shapes: B=32, NV=512, NQ=128, V_DIM=2048, Q_DIM=1024, HK=1536, H_OUT=8
//
// Round 1: fp32 SIMT baseline. Three NT-form tiled GEMMs (128x128x16 tiles,
// 8x8 per-thread micro-tile, 256 threads). Scratch in __device__ globals.
// ---------------------------------------------------------------------------

#define B_   32
#define NV_  512
#define NQ_  128
#define VD_  2048
#define QD_  1024
#define HK_  1536
#define HO_  8

// scratch: projected activations
__device__ float g_v[(size_t)B_ * NV_ * HK_];   // (16384, 1536) ~100 MB
__device__ float g_q[(size_t)B_ * NQ_ * HK_];   // (4096, 1536)  ~25 MB

// ---------------------------------------------------------------------------
// proj: C[m,n] = relu( sum_k A[m,k] * W[n,k] + bias[n] )
// A: (M,K) row-major, W: (N,K) row-major.  M%128==0, N%128==0, K%16==0.
// which==0 -> write g_v, which==1 -> write g_q
// ---------------------------------------------------------------------------
__global__ void __launch_bounds__(256, 2)
proj_kernel(const float* __restrict__ A, const float* __restrict__ W,
            const float* __restrict__ bias, int which,
            int M, int N, int K)
{
    __shared__ float As[16][132];
    __shared__ float Bs[16][132];

    float* __restrict__ Cout = (which == 0) ? g_v : g_q;

    const int bm  = blockIdx.x * 128;
    const int bn  = blockIdx.y * 128;
    const int tid = threadIdx.x;
    const int tx  = tid & 15;      // 0..15  -> n micro-tile
    const int ty  = tid >> 4;      // 0..15  -> m micro-tile

    float acc[8][8];
#pragma unroll
    for (int i = 0; i < 8; i++)
#pragma unroll
        for (int j = 0; j < 8; j++) acc[i][j] = 0.f;

    const float* __restrict__ Ag = A + (size_t)bm * K;
    const float* __restrict__ Bg = W + (size_t)bn * K;

    for (int k0 = 0; k0 < K; k0 += 16) {
        // load 128 rows x 16 k for A and B tiles: 512 float4 each, 2 per thread
#pragma unroll
        for (int l = 0; l < 2; l++) {
            int idx = tid + l * 256;       // 0..511
            int row = idx >> 2;            // 0..127
            int kq  = (idx & 3) << 2;      // 0,4,8,12
            float4 a = *(const float4*)(Ag + (size_t)row * K + k0 + kq);
            As[kq + 0][row] = a.x;
            As[kq + 1][row] = a.y;
            As[kq + 2][row] = a.z;
            As[kq + 3][row] = a.w;
            float4 b = *(const float4*)(Bg + (size_t)row * K + k0 + kq);
            Bs[kq + 0][row] = b.x;
            Bs[kq + 1][row] = b.y;
            Bs[kq + 2][row] = b.z;
            Bs[kq + 3][row] = b.w;
        }
        __syncthreads();

#pragma unroll
        for (int kk = 0; kk < 16; kk++) {
            float ar[8], br[8];
#pragma unroll
            for (int i = 0; i < 8; i++) ar[i] = As[kk][ty * 8 + i];
#pragma unroll
            for (int j = 0; j < 8; j++) br[j] = Bs[kk][tx * 8 + j];
#pragma unroll
            for (int i = 0; i < 8; i++)
#pragma unroll
                for (int j = 0; j < 8; j++)
                    acc[i][j] = fmaf(ar[i], br[j], acc[i][j]);
        }
        __syncthreads();
    }

    // epilogue: bias + relu, vectorized stores
#pragma unroll
    for (int i = 0; i < 8; i++) {
        size_t m = (size_t)(bm + ty * 8 + i);
#pragma unroll
        for (int jj = 0; jj < 2; jj++) {
            int n = bn + tx * 8 + jj * 4;
            float4 o;
            o.x = fmaxf(acc[i][jj * 4 + 0] + bias[n + 0], 0.f);
            o.y = fmaxf(acc[i][jj * 4 + 1] + bias[n + 1], 0.f);
            o.z = fmaxf(acc[i][jj * 4 + 2] + bias[n + 2], 0.f);
            o.w = fmaxf(acc[i][jj * 4 + 3] + bias[n + 3], 0.f);
            *(float4*)(Cout + m * N + n) = o;
        }
    }
}

// ---------------------------------------------------------------------------
// bilinear: for each (b,h):
//   out[bh, v, q] = sum_k g_v[b,v,k] * (h_mat[h,k] * g_q[b,q,k]) + h_bias[h]
// grid.x = v-tile (0..3), grid.y = b*8+h (0..255). N == 128 == one tile.
// ---------------------------------------------------------------------------
__global__ void __launch_bounds__(256, 2)
bilinear_kernel(const float* __restrict__ h_mat, const float* __restrict__ h_bias,
                float* __restrict__ out)
{
    __shared__ float As[16][132];
    __shared__ float Bs[16][132];

    const int bh = blockIdx.y;
    const int b  = bh >> 3;
    const int h  = bh & 7;
    const int bm = blockIdx.x * 128;   // v offset within NV_

    const float* __restrict__ Ag = g_v + ((size_t)b * NV_ + bm) * HK_;
    const float* __restrict__ Bg = g_q + (size_t)b * NQ_ * HK_;
    const float* __restrict__ hv = h_mat + (size_t)h * HK_;

    const int tid = threadIdx.x;
    const int tx  = tid & 15;
    const int ty  = tid >> 4;

    float acc[8][8];
#pragma unroll
    for (int i = 0; i < 8; i++)
#pragma unroll
        for (int j = 0; j < 8; j++) acc[i][j] = 0.f;

    for (int k0 = 0; k0 < HK_; k0 += 16) {
#pragma unroll
        for (int l = 0; l < 2; l++) {
            int idx = tid + l * 256;
            int row = idx >> 2;            // 0..127
            int kq  = (idx & 3) << 2;
            float4 a = *(const float4*)(Ag + (size_t)row * HK_ + k0 + kq);
            As[kq + 0][row] = a.x;
            As[kq + 1][row] = a.y;
            As[kq + 2][row] = a.z;
            As[kq + 3][row] = a.w;
            float4 qv = *(const float4*)(Bg + (size_t)row * HK_ + k0 + kq);
            float4 hh = *(const float4*)(hv + k0 + kq);
            Bs[kq + 0][row] = qv.x * hh.x;
            Bs[kq + 1][row] = qv.y * hh.y;
            Bs[kq + 2][row] = qv.z * hh.z;
            Bs[kq + 3][row] = qv.w * hh.w;
        }
        __syncthreads();

#pragma unroll
        for (int kk = 0; kk < 16; kk++) {
            float ar[8], br[8];
#pragma unroll
            for (int i = 0; i < 8; i++) ar[i] = As[kk][ty * 8 + i];
#pragma unroll
            for (int j = 0; j < 8; j++) br[j] = Bs[kk][tx * 8 + j];
#pragma unroll
            for (int i = 0; i < 8; i++)
#pragma unroll
                for (int j = 0; j < 8; j++)
                    acc[i][j] = fmaf(ar[i], br[j], acc[i][j]);
        }
        __syncthreads();
    }

    const float cb = h_bias[h];
    float* __restrict__ Co = out + ((size_t)bh * NV_ + bm) * NQ_;
#pragma unroll
    for (int i = 0; i < 8; i++) {
        size_t m = (size_t)(ty * 8 + i);
#pragma unroll
        for (int jj = 0; jj < 2; jj++) {
            int n = tx * 8 + jj * 4;
            float4 o;
            o.x = acc[i][jj * 4 + 0] + cb;
            o.y = acc[i][jj * 4 + 1] + cb;
            o.z = acc[i][jj * 4 + 2] + cb;
            o.w = acc[i][jj * 4 + 3] + cb;
            *(float4*)(Co + m * NQ_ + n) = o;
        }
    }
}

// ---------------------------------------------------------------------------
// inputs (metadata order): v, q, Wv, bv, Wq, bq, h_mat, h_bias
// output: float32 (32, 8, 512, 128)
// ---------------------------------------------------------------------------
extern "C" void kernel_launch(void* const* d_in, const int* in_sizes, int n_in,
                              void* d_out, int out_size)
{
    const float* v      = (const float*)d_in[0];
    const float* q      = (const float*)d_in[1];
    const float* Wv     = (const float*)d_in[2];
    const float* bv     = (const float*)d_in[3];
    const float* Wq     = (const float*)d_in[4];
    const float* bq     = (const float*)d_in[5];
    const float* h_mat  = (const float*)d_in[6];
    const float* h_bias = (const float*)d_in[7];
    float* out = (float*)d_out;

    // G1: v projection  (16384 x 2048) @ (1536 x 2048)^T -> g_v
    {
        dim3 grid((B_ * NV_) / 128, HK_ / 128);
        proj_kernel<<<grid, 256>>>(v, Wv, bv, /*which=*/0,
                                   B_ * NV_, HK_, VD_);
    }
    // G2: q projection  (4096 x 1024) @ (1536 x 1024)^T -> g_q
    {
        dim3 grid((B_ * NQ_) / 128, HK_ / 128);
        proj_kernel<<<grid, 256>>>(q, Wq, bq, /*which=*/1,
                                   B_ * NQ_, HK_, QD_);
    }
    // G3: batched bilinear contraction -> out
    {
        dim3 grid(NV_ / 128, B_ * HO_);
        bilinear_kernel<<<grid, 256>>>(h_mat, h_bias, out);
    }
}

// round 5
// speedup vs baseline: 2.7185x; 2.7185x over previous
#include <cuda_runtime.h>
#include <cstdint>

// ---------------------------------------------------------------------------
// BCNet via mma.sync tf32 tensor cores (plain sm_100 target — no tcgen05).
//  G1: g_v = relu(v @ Wv^T + bv)      M=16384 N=1536 K=2048
//  G2: g_q = relu(q @ Wq^T + bq)      M= 4096 N=1536 K=1024
//  G3: out[b,h,v,q] = sum_k g_v[b,v,k]*(h_mat[h,k]*g_q[b,q,k]) + h_bias[h]
//      per batch z: M=512 (v), N=1024 (8h x 128q), K=1536; BN=128 => h fixed
//      per CTA, h_mat folded into B staging.
// CTA tile 128x128, 8 warps of 64x32, K-chunk 32, double-buffered smem,
// register-staged pipeline, cvt.rna.tf32 (b32 dest) at staging.
// ---------------------------------------------------------------------------

#define B_   32
#define NV_  512
#define NQ_  128
#define VD_  2048
#define QD_  1024
#define HK_  1536
#define HO_  8

__device__ float g_v[(size_t)B_ * NV_ * HK_];   // ~100 MB scratch
__device__ float g_q[(size_t)B_ * NQ_ * HK_];   // ~25 MB scratch

#define BM 128
#define BN 128
#define KT 32
#define P  36                        // padded smem row stride (floats)
#define STG_FLOATS (BM * P)          // 4608 floats per tile
#define SMEM_FLOATS (4 * STG_FLOATS) // A0,B0,A1,B1
#define SMEM_BYTES  (SMEM_FLOATS * 4)

// tf32 destination is a .b32 register per PTX spec
__device__ __forceinline__ uint32_t rna(float x) {
    uint32_t y; asm("cvt.rna.tf32.f32 %0, %1;" : "=r"(y) : "f"(x)); return y;
}
__device__ __forceinline__ uint4 rna4(float4 v) {
    uint4 o; o.x = rna(v.x); o.y = rna(v.y); o.z = rna(v.z); o.w = rna(v.w);
    return o;
}

__device__ __forceinline__ void mma8(float& d0, float& d1, float& d2, float& d3,
                                     uint32_t a0, uint32_t a1, uint32_t a2, uint32_t a3,
                                     uint32_t b0, uint32_t b1) {
    asm volatile(
        "mma.sync.aligned.m16n8k8.row.col.f32.tf32.tf32.f32 "
        "{%0,%1,%2,%3}, {%4,%5,%6,%7}, {%8,%9}, {%0,%1,%2,%3};"
        : "+f"(d0), "+f"(d1), "+f"(d2), "+f"(d3)
        : "r"(a0), "r"(a1), "r"(a2), "r"(a3), "r"(b0), "r"(b1));
}

// sel 0: A=Ap(v),  B=Bp(Wv), C=g_v, epi relu(acc+bias[n]), C stride Ntot
// sel 1: A=Ap(q),  B=Bp(Wq), C=g_q, same
// sel 2: A=g_v[z], B=g_q[z]*h_mat[h], C=out scatter, epi acc+h_bias[h]
__global__ void __launch_bounds__(256)
gemm_mma(const float* __restrict__ Ap, const float* __restrict__ Bp,
         const float* __restrict__ bias, const float* __restrict__ h_mat,
         const float* __restrict__ h_bias, float* __restrict__ Cp,
         int Ntot, int K, int sel)
{
    extern __shared__ uint32_t sm[];
    uint32_t* bufA[2] = { sm,               sm + 2 * STG_FLOATS };
    uint32_t* bufB[2] = { sm + STG_FLOATS,  sm + 3 * STG_FLOATS };

    const int tid   = threadIdx.x;
    const int wid   = tid >> 5;
    const int lane  = tid & 31;
    const int group = lane >> 2;        // 0..7
    const int tig   = lane & 3;         // 0..3
    const int warp_m = (wid & 1) * 64;
    const int warp_n = (wid >> 1) * 32;

    const int bm = blockIdx.x * BM;
    const int bn = blockIdx.y * BN;
    const int z  = blockIdx.z;
    const int mode = (sel == 2);

    const float* __restrict__ Ag =
        (mode ? g_v + (size_t)z * NV_ * HK_ : Ap) + (size_t)bm * K;
    const float* __restrict__ Bg;
    const float* __restrict__ hmr = nullptr;
    if (mode) {
        Bg  = g_q + (size_t)z * NQ_ * HK_;          // row r = q index
        hmr = h_mat + (size_t)(bn >> 7) * K;        // h = bn/128
    } else {
        Bg = Bp + (size_t)bn * K;
    }

    // staging geometry: thread -> (row r0+32i, k-seg s4) for i=0..3
    const int r0 = tid >> 3;            // 0..31
    const int s4 = (tid & 7) * 4;       // 0,4,...,28

    float acc[4][4][4];
#pragma unroll
    for (int i = 0; i < 4; ++i)
#pragma unroll
        for (int j = 0; j < 4; ++j)
#pragma unroll
            for (int l = 0; l < 4; ++l) acc[i][j][l] = 0.f;

    float4 va[4], vb[4];

    const int NC = K / KT;

    // ---- prologue: stage chunk 0
    {
#pragma unroll
        for (int i = 0; i < 4; ++i) {
            const int r = r0 + 32 * i;
            va[i] = *(const float4*)(Ag + (size_t)r * K + s4);
            if (!mode) {
                vb[i] = *(const float4*)(Bg + (size_t)r * K + s4);
            } else {
                float4 t  = *(const float4*)(Bg + (size_t)r * K + s4);
                float4 hm = *(const float4*)(hmr + s4);
                t.x *= hm.x; t.y *= hm.y; t.z *= hm.z; t.w *= hm.w;
                vb[i] = t;
            }
        }
#pragma unroll
        for (int i = 0; i < 4; ++i) {
            const int r = r0 + 32 * i;
            *(uint4*)(bufA[0] + r * P + s4) = rna4(va[i]);
            *(uint4*)(bufB[0] + r * P + s4) = rna4(vb[i]);
        }
    }
    __syncthreads();

    for (int c = 0; c < NC; ++c) {
        const bool more = (c + 1 < NC);
        if (more) {
            const int k0 = (c + 1) * KT;
#pragma unroll
            for (int i = 0; i < 4; ++i) {
                const int r = r0 + 32 * i;
                va[i] = *(const float4*)(Ag + (size_t)r * K + k0 + s4);
                if (!mode) {
                    vb[i] = *(const float4*)(Bg + (size_t)r * K + k0 + s4);
                } else {
                    float4 t  = *(const float4*)(Bg + (size_t)r * K + k0 + s4);
                    float4 hm = *(const float4*)(hmr + k0 + s4);
                    t.x *= hm.x; t.y *= hm.y; t.z *= hm.z; t.w *= hm.w;
                    vb[i] = t;
                }
            }
        }

        // ---- compute chunk c from buffer c&1
        {
            const uint32_t* __restrict__ As = bufA[c & 1];
            const uint32_t* __restrict__ Bs = bufB[c & 1];
#pragma unroll
            for (int kk = 0; kk < 4; ++kk) {
                const int kb = kk * 8;
                uint32_t af[4][4];
#pragma unroll
                for (int mf = 0; mf < 4; ++mf) {
                    const int m = warp_m + mf * 16 + group;
                    af[mf][0] = As[m * P + kb + tig];
                    af[mf][1] = As[(m + 8) * P + kb + tig];
                    af[mf][2] = As[m * P + kb + tig + 4];
                    af[mf][3] = As[(m + 8) * P + kb + tig + 4];
                }
                uint32_t bf[4][2];
#pragma unroll
                for (int nf = 0; nf < 4; ++nf) {
                    const int n = warp_n + nf * 8 + group;
                    bf[nf][0] = Bs[n * P + kb + tig];
                    bf[nf][1] = Bs[n * P + kb + tig + 4];
                }
#pragma unroll
                for (int mf = 0; mf < 4; ++mf)
#pragma unroll
                    for (int nf = 0; nf < 4; ++nf)
                        mma8(acc[mf][nf][0], acc[mf][nf][1],
                             acc[mf][nf][2], acc[mf][nf][3],
                             af[mf][0], af[mf][1], af[mf][2], af[mf][3],
                             bf[nf][0], bf[nf][1]);
            }
        }

        if (more) {
            uint32_t* dA = bufA[(c + 1) & 1];
            uint32_t* dB = bufB[(c + 1) & 1];
#pragma unroll
            for (int i = 0; i < 4; ++i) {
                const int r = r0 + 32 * i;
                *(uint4*)(dA + r * P + s4) = rna4(va[i]);
                *(uint4*)(dB + r * P + s4) = rna4(vb[i]);
            }
        }
        __syncthreads();
    }

    // ---------------------------- epilogue --------------------------------
    if (!mode) {
        float* __restrict__ C = (sel == 0) ? g_v : g_q;
#pragma unroll
        for (int nf = 0; nf < 4; ++nf) {
            const int gn = bn + warp_n + nf * 8 + 2 * tig;
            const float b0 = __ldg(&bias[gn]);
            const float b1 = __ldg(&bias[gn + 1]);
#pragma unroll
            for (int mf = 0; mf < 4; ++mf) {
                const int gm = bm + warp_m + mf * 16 + group;
                float2 lo, hi;
                lo.x = fmaxf(acc[mf][nf][0] + b0, 0.f);
                lo.y = fmaxf(acc[mf][nf][1] + b1, 0.f);
                hi.x = fmaxf(acc[mf][nf][2] + b0, 0.f);
                hi.y = fmaxf(acc[mf][nf][3] + b1, 0.f);
                *(float2*)(C + (size_t)gm * Ntot + gn)       = lo;
                *(float2*)(C + (size_t)(gm + 8) * Ntot + gn) = hi;
            }
        }
    } else {
        const int h = bn >> 7;
        const float hb = __ldg(&h_bias[h]);
        float* __restrict__ C = Cp + ((size_t)(z * HO_ + h) * NV_) * NQ_;
#pragma unroll
        for (int nf = 0; nf < 4; ++nf) {
            const int qn = warp_n + nf * 8 + 2 * tig;     // 0..127
#pragma unroll
            for (int mf = 0; mf < 4; ++mf) {
                const int vm = bm + warp_m + mf * 16 + group;
                float2 lo, hi;
                lo.x = acc[mf][nf][0] + hb;
                lo.y = acc[mf][nf][1] + hb;
                hi.x = acc[mf][nf][2] + hb;
                hi.y = acc[mf][nf][3] + hb;
                *(float2*)(C + (size_t)vm * NQ_ + qn)       = lo;
                *(float2*)(C + (size_t)(vm + 8) * NQ_ + qn) = hi;
            }
        }
    }
}

// ---------------------------------------------------------------------------
// inputs: v, q, Wv, bv, Wq, bq, h_mat, h_bias ; output fp32 (32,8,512,128)
// ---------------------------------------------------------------------------
extern "C" void kernel_launch(void* const* d_in, const int* in_sizes, int n_in,
                              void* d_out, int out_size)
{
    const float* v      = (const float*)d_in[0];
    const float* q      = (const float*)d_in[1];
    const float* Wv     = (const float*)d_in[2];
    const float* bv     = (const float*)d_in[3];
    const float* Wq     = (const float*)d_in[4];
    const float* bq     = (const float*)d_in[5];
    const float* h_mat  = (const float*)d_in[6];
    const float* h_bias = (const float*)d_in[7];
    float* out = (float*)d_out;

    cudaFuncSetAttribute(gemm_mma, cudaFuncAttributeMaxDynamicSharedMemorySize,
                         SMEM_BYTES);

    // G1: v-proj -> g_v   (M=16384, N=1536, K=2048)
    gemm_mma<<<dim3((B_ * NV_) / BM, HK_ / BN, 1), 256, SMEM_BYTES>>>(
        v, Wv, bv, nullptr, nullptr, nullptr, HK_, VD_, 0);
    // G2: q-proj -> g_q   (M=4096, N=1536, K=1024)
    gemm_mma<<<dim3((B_ * NQ_) / BM, HK_ / BN, 1), 256, SMEM_BYTES>>>(
        q, Wq, bq, nullptr, nullptr, nullptr, HK_, QD_, 1);
    // G3: bilinear -> out (per batch: M=512, N=1024 = 8h x 128q, K=1536)
    gemm_mma<<<dim3(NV_ / BM, (HO_ * NQ_) / BN, B_), 256, SMEM_BYTES>>>(
        nullptr, nullptr, nullptr, h_mat, h_bias, out, HO_ * NQ_, HK_, 2);
}